// round 1
// baseline (speedup 1.0000x reference)
#include <cuda_runtime.h>
#include <math.h>

#define BATCH 2
#define SEQ   2048
#define DIM   4096
#define HQ    32
#define HK    8
#define HD    128
#define REP   4
#define MROWS (BATCH*SEQ)   // 4096

// Scratch buffers (allocation-free rule: __device__ globals)
__device__ float g_Q [(size_t)MROWS*HQ*HD];   // 67 MB
__device__ float g_K [(size_t)MROWS*HK*HD];   // 16.8 MB
__device__ float g_V [(size_t)MROWS*HK*HD];   // 16.8 MB
__device__ float g_AO[(size_t)MROWS*HQ*HD];   // 67 MB

// ---------------------------------------------------------------------------
// SGEMM: C[M,N] = A[M,K] @ B[K,N], all row-major, fp32.
// 128x128 block, BK=8, 8x8 per thread, 256 threads. M,N % 128 == 0, K % 8 == 0.
// ---------------------------------------------------------------------------
__global__ __launch_bounds__(256) void sgemm128(
    const float* __restrict__ A, const float* __restrict__ Bm,
    float* __restrict__ C, int M, int N, int K)
{
    __shared__ float As[8][128];
    __shared__ float Bs[8][128];

    const int tid = threadIdx.x;
    const int bc = blockIdx.x, br = blockIdx.y;
    const int tx = tid & 15, ty = tid >> 4;

    float acc[8][8];
#pragma unroll
    for (int i = 0; i < 8; i++)
#pragma unroll
        for (int j = 0; j < 8; j++) acc[i][j] = 0.f;

    const int a_row = tid >> 1;            // 0..127
    const int a_col = (tid & 1) * 4;       // 0 or 4
    const int b_row = tid >> 5;            // 0..7
    const int b_col = (tid & 31) * 4;      // 0..124

    const float* Aptr = A + (size_t)(br * 128 + a_row) * K + a_col;
    const float* Bptr = Bm + (size_t)b_row * N + bc * 128 + b_col;

    for (int k0 = 0; k0 < K; k0 += 8) {
        float4 av = *(const float4*)(Aptr + k0);
        As[a_col + 0][a_row] = av.x;
        As[a_col + 1][a_row] = av.y;
        As[a_col + 2][a_row] = av.z;
        As[a_col + 3][a_row] = av.w;
        *(float4*)&Bs[b_row][b_col] = *(const float4*)(Bptr + (size_t)k0 * N);
        __syncthreads();

#pragma unroll
        for (int k = 0; k < 8; k++) {
            float ar[8], brg[8];
#pragma unroll
            for (int i = 0; i < 8; i++) ar[i] = As[k][ty * 8 + i];
#pragma unroll
            for (int j = 0; j < 8; j++) brg[j] = Bs[k][tx * 8 + j];
#pragma unroll
            for (int i = 0; i < 8; i++)
#pragma unroll
                for (int j = 0; j < 8; j++)
                    acc[i][j] += ar[i] * brg[j];
        }
        __syncthreads();
    }

#pragma unroll
    for (int i = 0; i < 8; i++) {
        float* Crow = C + (size_t)(br * 128 + ty * 8 + i) * N + bc * 128 + tx * 8;
        *(float4*)(Crow + 0) = make_float4(acc[i][0], acc[i][1], acc[i][2], acc[i][3]);
        *(float4*)(Crow + 4) = make_float4(acc[i][4], acc[i][5], acc[i][6], acc[i][7]);
    }
}

// ---------------------------------------------------------------------------
// RoPE in-place on [BATCH, SEQ, heads, HD] (interleaved pairs).
// ---------------------------------------------------------------------------
__global__ void rope_kernel(float* __restrict__ X,
                            const float* __restrict__ cosv,
                            const float* __restrict__ sinv, int heads, int total)
{
    int idx = blockIdx.x * blockDim.x + threadIdx.x;
    if (idx >= total) return;
    int d  = idx & 63;                       // HD/2 = 64
    int h  = (idx >> 6) % heads;
    int bs = idx / (64 * heads);             // b*SEQ + s
    int s  = bs & (SEQ - 1);

    float c  = cosv[s * 64 + d];
    float sn = sinv[s * 64 + d];
    size_t base = ((size_t)bs * heads + h) * HD + 2 * d;
    float xr = X[base], xi = X[base + 1];
    X[base]     = xr * c - xi * sn;
    X[base + 1] = xr * sn + xi * c;
}

// ---------------------------------------------------------------------------
// Flash attention (non-causal, full softmax over SEQ keys).
// One CTA = one (b, head, 64-query tile). BQ=BK=64, HD=128, 256 threads.
// ---------------------------------------------------------------------------
#define BQT 64
#define BKT 64
#define KSS 132   // padded K/V row stride
#define SSS 65    // padded S row stride

__global__ __launch_bounds__(256) void flash_attn_kernel()
{
    extern __shared__ float sm[];
    float* Qs = sm;                    // 64*128
    float* Ks = Qs + BQT * HD;         // 64*132 (reused for V)
    float* Ss = Ks + BKT * KSS;        // 64*65
    __shared__ float row_m[BQT], row_l[BQT], row_scale[BQT];

    const int tid = threadIdx.x;
    const int tx = tid & 15, ty = tid >> 4;
    const int q0 = blockIdx.x * BQT;
    const int b  = blockIdx.y / HQ;
    const int h  = blockIdx.y % HQ;
    const int g  = h / REP;
    const float scale = 0.088388347648318447f;   // 1/sqrt(128)

    // load Q tile
#pragma unroll
    for (int it = tid; it < BQT * 32; it += 256) {
        int row = it >> 5, c4 = (it & 31) << 2;
        *(float4*)&Qs[row * HD + c4] =
            *(const float4*)&g_Q[(((size_t)(b * SEQ + q0 + row)) * HQ + h) * HD + c4];
    }
    if (tid < BQT) { row_m[tid] = -1e30f; row_l[tid] = 0.f; }

    float acc[4][8];
#pragma unroll
    for (int i = 0; i < 4; i++)
#pragma unroll
        for (int c = 0; c < 8; c++) acc[i][c] = 0.f;

    for (int kb = 0; kb < SEQ / BKT; kb++) {
        const int k0 = kb * BKT;
        // load K tile
#pragma unroll
        for (int it = tid; it < BKT * 32; it += 256) {
            int row = it >> 5, c4 = (it & 31) << 2;
            *(float4*)&Ks[row * KSS + c4] =
                *(const float4*)&g_K[(((size_t)(b * SEQ + k0 + row)) * HK + g) * HD + c4];
        }
        __syncthreads();

        // S = Q @ K^T  (4x4 per thread)
        float sacc[4][4];
#pragma unroll
        for (int i = 0; i < 4; i++)
#pragma unroll
            for (int j = 0; j < 4; j++) sacc[i][j] = 0.f;

#pragma unroll 8
        for (int d4 = 0; d4 < 32; d4++) {
            float4 qv[4], kv[4];
#pragma unroll
            for (int i = 0; i < 4; i++)
                qv[i] = *(const float4*)&Qs[(ty * 4 + i) * HD + d4 * 4];
#pragma unroll
            for (int j = 0; j < 4; j++)
                kv[j] = *(const float4*)&Ks[(tx * 4 + j) * KSS + d4 * 4];
#pragma unroll
            for (int i = 0; i < 4; i++)
#pragma unroll
                for (int j = 0; j < 4; j++) {
                    sacc[i][j] += qv[i].x * kv[j].x;
                    sacc[i][j] += qv[i].y * kv[j].y;
                    sacc[i][j] += qv[i].z * kv[j].z;
                    sacc[i][j] += qv[i].w * kv[j].w;
                }
        }
#pragma unroll
        for (int i = 0; i < 4; i++)
#pragma unroll
            for (int j = 0; j < 4; j++)
                Ss[(ty * 4 + i) * SSS + (tx * 4 + j)] = sacc[i][j] * scale;
        __syncthreads();

        // online softmax: one thread per query row
        if (tid < BQT) {
            int r = tid;
            float m_old = row_m[r];
            float mx = m_old;
#pragma unroll 8
            for (int j = 0; j < BKT; j++) mx = fmaxf(mx, Ss[r * SSS + j]);
            float sc = __expf(m_old - mx);
            float l = row_l[r] * sc;
#pragma unroll 8
            for (int j = 0; j < BKT; j++) {
                float p = __expf(Ss[r * SSS + j] - mx);
                Ss[r * SSS + j] = p;
                l += p;
            }
            row_m[r] = mx; row_l[r] = l; row_scale[r] = sc;
        }

        // load V tile into Ks buffer (disjoint from Ss; safe to overlap softmax)
#pragma unroll
        for (int it = tid; it < BKT * 32; it += 256) {
            int row = it >> 5, c4 = (it & 31) << 2;
            *(float4*)&Ks[row * KSS + c4] =
                *(const float4*)&g_V[(((size_t)(b * SEQ + k0 + row)) * HK + g) * HD + c4];
        }
        __syncthreads();

        // rescale accumulators and add P @ V
        float scr[4];
#pragma unroll
        for (int i = 0; i < 4; i++) scr[i] = row_scale[ty * 4 + i];
#pragma unroll
        for (int i = 0; i < 4; i++)
#pragma unroll
            for (int c = 0; c < 8; c++) acc[i][c] *= scr[i];

#pragma unroll 8
        for (int j = 0; j < BKT; j++) {
            float p[4];
#pragma unroll
            for (int i = 0; i < 4; i++) p[i] = Ss[(ty * 4 + i) * SSS + j];
            float4 v0 = *(const float4*)&Ks[j * KSS + tx * 8];
            float4 v1 = *(const float4*)&Ks[j * KSS + tx * 8 + 4];
#pragma unroll
            for (int i = 0; i < 4; i++) {
                acc[i][0] += p[i] * v0.x;  acc[i][1] += p[i] * v0.y;
                acc[i][2] += p[i] * v0.z;  acc[i][3] += p[i] * v0.w;
                acc[i][4] += p[i] * v1.x;  acc[i][5] += p[i] * v1.y;
                acc[i][6] += p[i] * v1.z;  acc[i][7] += p[i] * v1.w;
            }
        }
        __syncthreads();
    }

    // epilogue: divide by l, write out
    float invl[4];
#pragma unroll
    for (int i = 0; i < 4; i++) invl[i] = 1.f / row_l[ty * 4 + i];
#pragma unroll
    for (int i = 0; i < 4; i++) {
        size_t base = (((size_t)(b * SEQ + q0 + ty * 4 + i)) * HQ + h) * HD + tx * 8;
        *(float4*)&g_AO[base] = make_float4(acc[i][0] * invl[i], acc[i][1] * invl[i],
                                            acc[i][2] * invl[i], acc[i][3] * invl[i]);
        *(float4*)&g_AO[base + 4] = make_float4(acc[i][4] * invl[i], acc[i][5] * invl[i],
                                                acc[i][6] * invl[i], acc[i][7] * invl[i]);
    }
}

// ---------------------------------------------------------------------------
extern "C" void kernel_launch(void* const* d_in, const int* in_sizes, int n_in,
                              void* d_out, int out_size)
{
    const float* x    = (const float*)d_in[0];
    const float* wq   = (const float*)d_in[1];
    const float* wk   = (const float*)d_in[2];
    const float* wv   = (const float*)d_in[3];
    const float* wo   = (const float*)d_in[4];
    const float* fcos = (const float*)d_in[5];
    const float* fsin = (const float*)d_in[6];
    float* out = (float*)d_out;

    float *Qp, *Kp, *Vp, *AOp;
    cudaGetSymbolAddress((void**)&Qp,  g_Q);
    cudaGetSymbolAddress((void**)&Kp,  g_K);
    cudaGetSymbolAddress((void**)&Vp,  g_V);
    cudaGetSymbolAddress((void**)&AOp, g_AO);

    // QKV projections
    sgemm128<<<dim3((HQ*HD)/128, MROWS/128), 256>>>(x, wq, Qp, MROWS, HQ*HD, DIM);
    sgemm128<<<dim3((HK*HD)/128, MROWS/128), 256>>>(x, wk, Kp, MROWS, HK*HD, DIM);
    sgemm128<<<dim3((HK*HD)/128, MROWS/128), 256>>>(x, wv, Vp, MROWS, HK*HD, DIM);

    // RoPE on Q and K
    {
        int nq = BATCH * SEQ * HQ * (HD / 2);
        rope_kernel<<<(nq + 255) / 256, 256>>>(Qp, fcos, fsin, HQ, nq);
        int nk = BATCH * SEQ * HK * (HD / 2);
        rope_kernel<<<(nk + 255) / 256, 256>>>(Kp, fcos, fsin, HK, nk);
    }

    // flash attention
    {
        const int smem = (BQT * HD + BKT * KSS + BQT * SSS) * (int)sizeof(float); // 83,200 B
        cudaFuncSetAttribute(flash_attn_kernel,
                             cudaFuncAttributeMaxDynamicSharedMemorySize, smem);
        flash_attn_kernel<<<dim3(SEQ / BQT, BATCH * HQ), 256, smem>>>();
    }

    // output projection
    sgemm128<<<dim3(DIM/128, MROWS/128), 256>>>(AOp, wo, out, MROWS, DIM, DIM);
}

// round 2
// speedup vs baseline: 1.6698x; 1.6698x over previous
#include <cuda_runtime.h>
#include <math.h>
#include <stdint.h>

#define BATCH 2
#define SEQ   2048
#define DIM   4096
#define HQ    32
#define HK    8
#define HD    128
#define REP   4
#define MROWS (BATCH*SEQ)   // 4096

// Scratch buffers (allocation-free rule: __device__ globals)
__device__ float g_Q [(size_t)MROWS*HQ*HD];
__device__ float g_K [(size_t)MROWS*HK*HD];
__device__ float g_V [(size_t)MROWS*HK*HD];
__device__ float g_AO[(size_t)MROWS*HQ*HD];

__device__ __forceinline__ uint32_t f2tf32(float f) {
    uint32_t u;
    asm("cvt.rna.tf32.f32 %0, %1;" : "=r"(u) : "f"(f));
    return u;
}

#define MMA_TF32(d, a, b) \
    asm volatile("mma.sync.aligned.m16n8k8.row.col.f32.tf32.tf32.f32 " \
        "{%0,%1,%2,%3},{%4,%5,%6,%7},{%8,%9},{%0,%1,%2,%3};" \
        : "+f"(d[0]), "+f"(d[1]), "+f"(d[2]), "+f"(d[3]) \
        : "r"(a[0]), "r"(a[1]), "r"(a[2]), "r"(a[3]), "r"(b[0]), "r"(b[1]))

// ---------------------------------------------------------------------------
// TF32 tensor-core GEMM: C[M,N] = A[M,K] @ B[K,N], row-major fp32 in/out.
// 128x128x32 tile, 256 threads (8 warps, 4x2 warp grid, 32x64 warp tile).
// Double-buffered smem via register staging. M%128==0, N%128==0, K%32==0.
// smem: As [2][128][36] u32 + Bs [2][32][136] u32 = 71680 B (dynamic).
// ---------------------------------------------------------------------------
#define AS_STRIDE 36
#define BS_STRIDE 136
#define AS_BUF (128*AS_STRIDE)
#define BS_BUF (32*BS_STRIDE)
#define GEMM_SMEM ((2*AS_BUF + 2*BS_BUF)*4)

__global__ __launch_bounds__(256) void gemm_tf32(
    const float* __restrict__ A, const float* __restrict__ B,
    float* __restrict__ C, int M, int N, int K)
{
    extern __shared__ uint32_t smg[];
    uint32_t* Asm = smg;                 // [2][128][36]
    uint32_t* Bsm = smg + 2*AS_BUF;      // [2][32][136]

    const int tid  = threadIdx.x;
    const int br   = blockIdx.y, bc = blockIdx.x;
    const int warp = tid >> 5, lane = tid & 31;
    const int g    = lane >> 2, t = lane & 3;
    const int wr   = warp & 3;           // 0..3 -> rows wr*32
    const int wc   = warp >> 2;          // 0..1 -> cols wc*64

    float acc[2][8][4];
#pragma unroll
    for (int i = 0; i < 2; i++)
#pragma unroll
        for (int j = 0; j < 8; j++)
#pragma unroll
            for (int r = 0; r < 4; r++) acc[i][j][r] = 0.f;

    float4 arg[4], brg[4];

    const int nkt = K / 32;

    // ---- prologue: load tile 0 ----
#pragma unroll
    for (int i = 0; i < 4; i++) {
        int s = tid + 256 * i;
        arg[i] = *(const float4*)&A[(size_t)(br*128 + (s >> 3)) * K + (s & 7) * 4];
        brg[i] = *(const float4*)&B[(size_t)(s >> 5) * N + bc*128 + (s & 31) * 4];
    }
    {
        uint32_t* Ab = Asm; uint32_t* Bb = Bsm;
#pragma unroll
        for (int i = 0; i < 4; i++) {
            int s = tid + 256 * i;
            int r = s >> 3, c4 = (s & 7) * 4;
            Ab[r*AS_STRIDE + c4 + 0] = f2tf32(arg[i].x);
            Ab[r*AS_STRIDE + c4 + 1] = f2tf32(arg[i].y);
            Ab[r*AS_STRIDE + c4 + 2] = f2tf32(arg[i].z);
            Ab[r*AS_STRIDE + c4 + 3] = f2tf32(arg[i].w);
            int rb = s >> 5, cb = (s & 31) * 4;
            Bb[rb*BS_STRIDE + cb + 0] = f2tf32(brg[i].x);
            Bb[rb*BS_STRIDE + cb + 1] = f2tf32(brg[i].y);
            Bb[rb*BS_STRIDE + cb + 2] = f2tf32(brg[i].z);
            Bb[rb*BS_STRIDE + cb + 3] = f2tf32(brg[i].w);
        }
    }
    __syncthreads();

    int cur = 0;
    for (int kt = 0; kt < nkt; kt++) {
        // prefetch next tile into registers (overlaps compute)
        if (kt + 1 < nkt) {
#pragma unroll
            for (int i = 0; i < 4; i++) {
                int s = tid + 256 * i;
                arg[i] = *(const float4*)&A[(size_t)(br*128 + (s >> 3)) * K
                                            + (kt+1)*32 + (s & 7) * 4];
                brg[i] = *(const float4*)&B[(size_t)((kt+1)*32 + (s >> 5)) * N
                                            + bc*128 + (s & 31) * 4];
            }
        }

        const uint32_t* Ab = Asm + cur * AS_BUF;
        const uint32_t* Bb = Bsm + cur * BS_BUF;

#pragma unroll
        for (int ks = 0; ks < 4; ks++) {
            const int kb = ks * 8;
            uint32_t af[2][4], bf[8][2];
#pragma unroll
            for (int i = 0; i < 2; i++) {
                int r0 = wr*32 + i*16 + g;
                af[i][0] = Ab[ r0      * AS_STRIDE + kb + t];
                af[i][1] = Ab[(r0 + 8) * AS_STRIDE + kb + t];
                af[i][2] = Ab[ r0      * AS_STRIDE + kb + t + 4];
                af[i][3] = Ab[(r0 + 8) * AS_STRIDE + kb + t + 4];
            }
#pragma unroll
            for (int j = 0; j < 8; j++) {
                int c0 = wc*64 + j*8 + g;
                bf[j][0] = Bb[(kb + t)     * BS_STRIDE + c0];
                bf[j][1] = Bb[(kb + t + 4) * BS_STRIDE + c0];
            }
#pragma unroll
            for (int i = 0; i < 2; i++)
#pragma unroll
                for (int j = 0; j < 8; j++)
                    MMA_TF32(acc[i][j], af[i], bf[j]);
        }

        if (kt + 1 < nkt) {
            uint32_t* Aw = Asm + (cur ^ 1) * AS_BUF;
            uint32_t* Bw = Bsm + (cur ^ 1) * BS_BUF;
#pragma unroll
            for (int i = 0; i < 4; i++) {
                int s = tid + 256 * i;
                int r = s >> 3, c4 = (s & 7) * 4;
                Aw[r*AS_STRIDE + c4 + 0] = f2tf32(arg[i].x);
                Aw[r*AS_STRIDE + c4 + 1] = f2tf32(arg[i].y);
                Aw[r*AS_STRIDE + c4 + 2] = f2tf32(arg[i].z);
                Aw[r*AS_STRIDE + c4 + 3] = f2tf32(arg[i].w);
                int rb = s >> 5, cb = (s & 31) * 4;
                Bw[rb*BS_STRIDE + cb + 0] = f2tf32(brg[i].x);
                Bw[rb*BS_STRIDE + cb + 1] = f2tf32(brg[i].y);
                Bw[rb*BS_STRIDE + cb + 2] = f2tf32(brg[i].z);
                Bw[rb*BS_STRIDE + cb + 3] = f2tf32(brg[i].w);
            }
            __syncthreads();
            cur ^= 1;
        }
    }

    // epilogue
#pragma unroll
    for (int i = 0; i < 2; i++) {
#pragma unroll
        for (int j = 0; j < 8; j++) {
            int row = br*128 + wr*32 + i*16 + g;
            int col = bc*128 + wc*64 + j*8 + 2*t;
            float2 v01 = make_float2(acc[i][j][0], acc[i][j][1]);
            float2 v23 = make_float2(acc[i][j][2], acc[i][j][3]);
            *(float2*)&C[(size_t)row * N + col]       = v01;
            *(float2*)&C[(size_t)(row + 8) * N + col] = v23;
        }
    }
}

// ---------------------------------------------------------------------------
// RoPE in-place on [BATCH, SEQ, heads, HD] (interleaved pairs).
// ---------------------------------------------------------------------------
__global__ void rope_kernel(float* __restrict__ X,
                            const float* __restrict__ cosv,
                            const float* __restrict__ sinv, int heads, int total)
{
    int idx = blockIdx.x * blockDim.x + threadIdx.x;
    if (idx >= total) return;
    int d  = idx & 63;
    int h  = (idx >> 6) % heads;
    int bs = idx / (64 * heads);
    int s  = bs & (SEQ - 1);

    float c  = cosv[s * 64 + d];
    float sn = sinv[s * 64 + d];
    size_t base = ((size_t)bs * heads + h) * HD + 2 * d;
    float xr = X[base], xi = X[base + 1];
    X[base]     = xr * c - xi * sn;
    X[base + 1] = xr * sn + xi * c;
}

// ---------------------------------------------------------------------------
// Flash attention (fp32 SIMT, unchanged from R1 — tensorized next round).
// ---------------------------------------------------------------------------
#define BQT 64
#define BKT 64
#define KSS 132
#define SSS 65

__global__ __launch_bounds__(256) void flash_attn_kernel()
{
    extern __shared__ float sm[];
    float* Qs = sm;
    float* Ks = Qs + BQT * HD;
    float* Ss = Ks + BKT * KSS;
    __shared__ float row_m[BQT], row_l[BQT], row_scale[BQT];

    const int tid = threadIdx.x;
    const int tx = tid & 15, ty = tid >> 4;
    const int q0 = blockIdx.x * BQT;
    const int b  = blockIdx.y / HQ;
    const int h  = blockIdx.y % HQ;
    const int g  = h / REP;
    const float scale = 0.088388347648318447f;

#pragma unroll
    for (int it = tid; it < BQT * 32; it += 256) {
        int row = it >> 5, c4 = (it & 31) << 2;
        *(float4*)&Qs[row * HD + c4] =
            *(const float4*)&g_Q[(((size_t)(b * SEQ + q0 + row)) * HQ + h) * HD + c4];
    }
    if (tid < BQT) { row_m[tid] = -1e30f; row_l[tid] = 0.f; }

    float acc[4][8];
#pragma unroll
    for (int i = 0; i < 4; i++)
#pragma unroll
        for (int c = 0; c < 8; c++) acc[i][c] = 0.f;

    for (int kb = 0; kb < SEQ / BKT; kb++) {
        const int k0 = kb * BKT;
#pragma unroll
        for (int it = tid; it < BKT * 32; it += 256) {
            int row = it >> 5, c4 = (it & 31) << 2;
            *(float4*)&Ks[row * KSS + c4] =
                *(const float4*)&g_K[(((size_t)(b * SEQ + k0 + row)) * HK + g) * HD + c4];
        }
        __syncthreads();

        float sacc[4][4];
#pragma unroll
        for (int i = 0; i < 4; i++)
#pragma unroll
            for (int j = 0; j < 4; j++) sacc[i][j] = 0.f;

#pragma unroll 8
        for (int d4 = 0; d4 < 32; d4++) {
            float4 qv[4], kv[4];
#pragma unroll
            for (int i = 0; i < 4; i++)
                qv[i] = *(const float4*)&Qs[(ty * 4 + i) * HD + d4 * 4];
#pragma unroll
            for (int j = 0; j < 4; j++)
                kv[j] = *(const float4*)&Ks[(tx * 4 + j) * KSS + d4 * 4];
#pragma unroll
            for (int i = 0; i < 4; i++)
#pragma unroll
                for (int j = 0; j < 4; j++) {
                    sacc[i][j] += qv[i].x * kv[j].x;
                    sacc[i][j] += qv[i].y * kv[j].y;
                    sacc[i][j] += qv[i].z * kv[j].z;
                    sacc[i][j] += qv[i].w * kv[j].w;
                }
        }
#pragma unroll
        for (int i = 0; i < 4; i++)
#pragma unroll
            for (int j = 0; j < 4; j++)
                Ss[(ty * 4 + i) * SSS + (tx * 4 + j)] = sacc[i][j] * scale;
        __syncthreads();

        if (tid < BQT) {
            int r = tid;
            float m_old = row_m[r];
            float mx = m_old;
#pragma unroll 8
            for (int j = 0; j < BKT; j++) mx = fmaxf(mx, Ss[r * SSS + j]);
            float sc = __expf(m_old - mx);
            float l = row_l[r] * sc;
#pragma unroll 8
            for (int j = 0; j < BKT; j++) {
                float p = __expf(Ss[r * SSS + j] - mx);
                Ss[r * SSS + j] = p;
                l += p;
            }
            row_m[r] = mx; row_l[r] = l; row_scale[r] = sc;
        }

#pragma unroll
        for (int it = tid; it < BKT * 32; it += 256) {
            int row = it >> 5, c4 = (it & 31) << 2;
            *(float4*)&Ks[row * KSS + c4] =
                *(const float4*)&g_V[(((size_t)(b * SEQ + k0 + row)) * HK + g) * HD + c4];
        }
        __syncthreads();

        float scr[4];
#pragma unroll
        for (int i = 0; i < 4; i++) scr[i] = row_scale[ty * 4 + i];
#pragma unroll
        for (int i = 0; i < 4; i++)
#pragma unroll
            for (int c = 0; c < 8; c++) acc[i][c] *= scr[i];

#pragma unroll 8
        for (int j = 0; j < BKT; j++) {
            float p[4];
#pragma unroll
            for (int i = 0; i < 4; i++) p[i] = Ss[(ty * 4 + i) * SSS + j];
            float4 v0 = *(const float4*)&Ks[j * KSS + tx * 8];
            float4 v1 = *(const float4*)&Ks[j * KSS + tx * 8 + 4];
#pragma unroll
            for (int i = 0; i < 4; i++) {
                acc[i][0] += p[i] * v0.x;  acc[i][1] += p[i] * v0.y;
                acc[i][2] += p[i] * v0.z;  acc[i][3] += p[i] * v0.w;
                acc[i][4] += p[i] * v1.x;  acc[i][5] += p[i] * v1.y;
                acc[i][6] += p[i] * v1.z;  acc[i][7] += p[i] * v1.w;
            }
        }
        __syncthreads();
    }

    float invl[4];
#pragma unroll
    for (int i = 0; i < 4; i++) invl[i] = 1.f / row_l[ty * 4 + i];
#pragma unroll
    for (int i = 0; i < 4; i++) {
        size_t base = (((size_t)(b * SEQ + q0 + ty * 4 + i)) * HQ + h) * HD + tx * 8;
        *(float4*)&g_AO[base] = make_float4(acc[i][0] * invl[i], acc[i][1] * invl[i],
                                            acc[i][2] * invl[i], acc[i][3] * invl[i]);
        *(float4*)&g_AO[base + 4] = make_float4(acc[i][4] * invl[i], acc[i][5] * invl[i],
                                                acc[i][6] * invl[i], acc[i][7] * invl[i]);
    }
}

// ---------------------------------------------------------------------------
extern "C" void kernel_launch(void* const* d_in, const int* in_sizes, int n_in,
                              void* d_out, int out_size)
{
    const float* x    = (const float*)d_in[0];
    const float* wq   = (const float*)d_in[1];
    const float* wk   = (const float*)d_in[2];
    const float* wv   = (const float*)d_in[3];
    const float* wo   = (const float*)d_in[4];
    const float* fcos = (const float*)d_in[5];
    const float* fsin = (const float*)d_in[6];
    float* out = (float*)d_out;

    float *Qp, *Kp, *Vp, *AOp;
    cudaGetSymbolAddress((void**)&Qp,  g_Q);
    cudaGetSymbolAddress((void**)&Kp,  g_K);
    cudaGetSymbolAddress((void**)&Vp,  g_V);
    cudaGetSymbolAddress((void**)&AOp, g_AO);

    cudaFuncSetAttribute(gemm_tf32,
                         cudaFuncAttributeMaxDynamicSharedMemorySize, GEMM_SMEM);

    // QKV projections (tf32 tensor cores)
    gemm_tf32<<<dim3((HQ*HD)/128, MROWS/128), 256, GEMM_SMEM>>>(x, wq, Qp, MROWS, HQ*HD, DIM);
    gemm_tf32<<<dim3((HK*HD)/128, MROWS/128), 256, GEMM_SMEM>>>(x, wk, Kp, MROWS, HK*HD, DIM);
    gemm_tf32<<<dim3((HK*HD)/128, MROWS/128), 256, GEMM_SMEM>>>(x, wv, Vp, MROWS, HK*HD, DIM);

    // RoPE on Q and K
    {
        int nq = BATCH * SEQ * HQ * (HD / 2);
        rope_kernel<<<(nq + 255) / 256, 256>>>(Qp, fcos, fsin, HQ, nq);
        int nk = BATCH * SEQ * HK * (HD / 2);
        rope_kernel<<<(nk + 255) / 256, 256>>>(Kp, fcos, fsin, HK, nk);
    }

    // flash attention (fp32)
    {
        const int smem = (BQT * HD + BKT * KSS + BQT * SSS) * (int)sizeof(float);
        cudaFuncSetAttribute(flash_attn_kernel,
                             cudaFuncAttributeMaxDynamicSharedMemorySize, smem);
        flash_attn_kernel<<<dim3(SEQ / BQT, BATCH * HQ), 256, smem>>>();
    }

    // output projection (tf32 tensor cores)
    gemm_tf32<<<dim3(DIM/128, MROWS/128), 256, GEMM_SMEM>>>(AOp, wo, out, MROWS, DIM, DIM);
}

// round 3
// speedup vs baseline: 4.0468x; 2.4235x over previous
#include <cuda_runtime.h>
#include <cuda_bf16.h>
#include <math.h>
#include <stdint.h>

#define BATCH 2
#define SEQ   2048
#define DIM   4096
#define HQ    32
#define HK    8
#define HD    128
#define REP   4
#define MROWS (BATCH*SEQ)   // 4096

// fp32 scratch
__device__ float g_Q [(size_t)MROWS*HQ*HD];
__device__ float g_K [(size_t)MROWS*HK*HD];
__device__ float g_V [(size_t)MROWS*HK*HD];
__device__ float g_AO[(size_t)MROWS*HQ*HD];

// bf16 hi/lo planes
__device__ __nv_bfloat16 g_Xh [(size_t)MROWS*DIM],   g_Xl [(size_t)MROWS*DIM];
__device__ __nv_bfloat16 g_Wqh[(size_t)DIM*HQ*HD],   g_Wql[(size_t)DIM*HQ*HD];
__device__ __nv_bfloat16 g_Wkh[(size_t)DIM*HK*HD],   g_Wkl[(size_t)DIM*HK*HD];
__device__ __nv_bfloat16 g_Wvh[(size_t)DIM*HK*HD],   g_Wvl[(size_t)DIM*HK*HD];
__device__ __nv_bfloat16 g_Woh[(size_t)DIM*DIM],     g_Wol[(size_t)DIM*DIM];
__device__ __nv_bfloat16 g_Qh [(size_t)MROWS*HQ*HD], g_Ql [(size_t)MROWS*HQ*HD];
__device__ __nv_bfloat16 g_Kh [(size_t)MROWS*HK*HD], g_Kl [(size_t)MROWS*HK*HD];
__device__ __nv_bfloat16 g_Vh [(size_t)MROWS*HK*HD], g_Vl [(size_t)MROWS*HK*HD];
__device__ __nv_bfloat16 g_AOh[(size_t)MROWS*HQ*HD], g_AOl[(size_t)MROWS*HQ*HD];

// ---------------- PTX helpers ----------------
#define LDSM4(R0,R1,R2,R3,A) \
    asm volatile("ldmatrix.sync.aligned.m8n8.x4.shared.b16 {%0,%1,%2,%3},[%4];" \
        : "=r"(R0),"=r"(R1),"=r"(R2),"=r"(R3) : "r"(A))
#define LDSM4T(R0,R1,R2,R3,A) \
    asm volatile("ldmatrix.sync.aligned.m8n8.x4.trans.shared.b16 {%0,%1,%2,%3},[%4];" \
        : "=r"(R0),"=r"(R1),"=r"(R2),"=r"(R3) : "r"(A))
#define MMABF16(D,A0,A1,A2,A3,B0,B1) \
    asm volatile("mma.sync.aligned.m16n8k16.row.col.f32.bf16.bf16.f32 " \
        "{%0,%1,%2,%3},{%4,%5,%6,%7},{%8,%9},{%0,%1,%2,%3};" \
        : "+f"(D[0]),"+f"(D[1]),"+f"(D[2]),"+f"(D[3]) \
        : "r"(A0),"r"(A1),"r"(A2),"r"(A3),"r"(B0),"r"(B1))
#define CP16(DST,SRC) \
    asm volatile("cp.async.cg.shared.global [%0],[%1],16;" :: "r"(DST),"l"(SRC))
#define CP_COMMIT asm volatile("cp.async.commit_group;" ::: "memory")
#define CP_WAIT1  asm volatile("cp.async.wait_group 1;" ::: "memory")
#define CP_WAIT0  asm volatile("cp.async.wait_group 0;" ::: "memory")

__device__ __forceinline__ uint32_t smem_u32(const void* p) {
    return (uint32_t)__cvta_generic_to_shared(p);
}
__device__ __forceinline__ void bsplit2(float x0, float x1, uint32_t& h, uint32_t& l) {
    __nv_bfloat16 h0 = __float2bfloat16(x0), h1 = __float2bfloat16(x1);
    float r0 = x0 - __bfloat162float(h0), r1 = x1 - __bfloat162float(h1);
    __nv_bfloat162 hh; hh.x = h0; hh.y = h1;
    __nv_bfloat162 ll; ll.x = __float2bfloat16(r0); ll.y = __float2bfloat16(r1);
    h = *(uint32_t*)&hh; l = *(uint32_t*)&ll;
}

// ---------------------------------------------------------------------------
// Split fp32 -> (hi, lo) bf16 planes, optional scale.
// ---------------------------------------------------------------------------
__global__ void cvt_split(const float* __restrict__ src,
                          __nv_bfloat16* __restrict__ hi,
                          __nv_bfloat16* __restrict__ lo, int n4, float scale)
{
    int i = blockIdx.x * blockDim.x + threadIdx.x;
    if (i >= n4) return;
    float4 v = ((const float4*)src)[i];
    v.x *= scale; v.y *= scale; v.z *= scale; v.w *= scale;
    uint32_t h01, l01, h23, l23;
    bsplit2(v.x, v.y, h01, l01);
    bsplit2(v.z, v.w, h23, l23);
    ((uint2*)hi)[i] = make_uint2(h01, h23);
    ((uint2*)lo)[i] = make_uint2(l01, l23);
}

// ---------------------------------------------------------------------------
// RoPE in-place (fp32).
// ---------------------------------------------------------------------------
__global__ void rope_kernel(float* __restrict__ X,
                            const float* __restrict__ cosv,
                            const float* __restrict__ sinv, int heads, int total)
{
    int idx = blockIdx.x * blockDim.x + threadIdx.x;
    if (idx >= total) return;
    int d  = idx & 63;
    int h  = (idx >> 6) % heads;
    int bs = idx / (64 * heads);
    int s  = bs & (SEQ - 1);
    float c  = cosv[s * 64 + d];
    float sn = sinv[s * 64 + d];
    size_t base = ((size_t)bs * heads + h) * HD + 2 * d;
    float xr = X[base], xi = X[base + 1];
    X[base]     = xr * c - xi * sn;
    X[base + 1] = xr * sn + xi * c;
}

// ---------------------------------------------------------------------------
// bf16-split GEMM: C[M,N] fp32 = A@B, A/B given as hi/lo bf16 planes.
// 128x128x32 tile, 256 thr, 8 warps (4x2), cp.async 2-stage, ldmatrix feeds.
// ---------------------------------------------------------------------------
#define G_SA 40     // A smem row stride (bf16)
#define G_SB 136    // B smem k-row stride (bf16)
#define G_AH 0
#define G_AL 5120   // 128*40
#define G_BH 10240
#define G_BL 14592  // +32*136
#define G_ST 18944  // stage stride (bf16)
#define GEMM_SMEM (2*G_ST*2)  // bytes

__global__ __launch_bounds__(256,2) void gemm_bs(
    const __nv_bfloat16* __restrict__ Ah, const __nv_bfloat16* __restrict__ Al,
    const __nv_bfloat16* __restrict__ Bh, const __nv_bfloat16* __restrict__ Bl,
    float* __restrict__ C, int M, int N, int K)
{
    extern __shared__ __align__(16) __nv_bfloat16 smg[];
    const uint32_t smb = smem_u32(smg);

    const int tid  = threadIdx.x;
    const int br = blockIdx.y, bc = blockIdx.x;
    const int warp = tid >> 5, lane = tid & 31;
    const int wr = warp & 3, wc = warp >> 2;

    float acc[2][8][4];
#pragma unroll
    for (int i = 0; i < 2; i++)
#pragma unroll
        for (int j = 0; j < 8; j++)
#pragma unroll
            for (int r = 0; r < 4; r++) acc[i][j][r] = 0.f;

    // ldmatrix lane offsets
    const int a_row = (lane & 7) + 8 * ((lane >> 3) & 1);
    const int a_k   = 8 * (lane >> 4);
    const int b_kr  = (lane & 7) + 8 * ((lane >> 3) & 1);
    const int b_n   = 8 * (lane >> 4);

    const int nkt = K / 32;

    // async stage loader
    const int ar0 = tid >> 2, ac0 = (tid & 3) * 8;          // A: 2 iters (+64 rows)
    const int bk0 = tid >> 4, bn0 = (tid & 15) * 8;         // B: 2 iters (+16 k)
#define GEMM_ISSUE(KT, BUF) do {                                               \
    int _sb = (BUF) * G_ST;                                                    \
    _Pragma("unroll")                                                          \
    for (int _j = 0; _j < 2; _j++) {                                           \
        int _r = ar0 + _j * 64;                                                \
        size_t _go = (size_t)(br*128 + _r) * K + (KT)*32 + ac0;                \
        CP16(smb + (_sb + G_AH + _r*G_SA + ac0)*2, Ah + _go);                  \
        CP16(smb + (_sb + G_AL + _r*G_SA + ac0)*2, Al + _go);                  \
        int _k = bk0 + _j * 16;                                                \
        size_t _gb = (size_t)((KT)*32 + _k) * N + bc*128 + bn0;                \
        CP16(smb + (_sb + G_BH + _k*G_SB + bn0)*2, Bh + _gb);                  \
        CP16(smb + (_sb + G_BL + _k*G_SB + bn0)*2, Bl + _gb);                  \
    } } while (0)

    GEMM_ISSUE(0, 0); CP_COMMIT;
    if (nkt > 1) { GEMM_ISSUE(1, 1); } CP_COMMIT;

    for (int kt = 0; kt < nkt; kt++) {
        if (kt < nkt - 2) { CP_WAIT1; } else { CP_WAIT0; }
        __syncthreads();
        const int sb = (kt & 1) * G_ST;

#pragma unroll
        for (int ks = 0; ks < 2; ks++) {
            uint32_t ah[2][4], al[2][4];
#pragma unroll
            for (int i = 0; i < 2; i++) {
                uint32_t addr = smb + (sb + G_AH +
                    (wr*32 + i*16 + a_row)*G_SA + ks*16 + a_k) * 2;
                LDSM4(ah[i][0], ah[i][1], ah[i][2], ah[i][3], addr);
                LDSM4(al[i][0], al[i][1], al[i][2], al[i][3], addr + (G_AL-G_AH)*2);
            }
#pragma unroll
            for (int jp = 0; jp < 4; jp++) {
                uint32_t bh[4], bl[4];
                uint32_t addr = smb + (sb + G_BH +
                    (ks*16 + b_kr)*G_SB + wc*64 + jp*16 + b_n) * 2;
                LDSM4T(bh[0], bh[1], bh[2], bh[3], addr);
                LDSM4T(bl[0], bl[1], bl[2], bl[3], addr + (G_BL-G_BH)*2);
#pragma unroll
                for (int i = 0; i < 2; i++) {
#pragma unroll
                    for (int jj = 0; jj < 2; jj++) {
                        float* d = acc[i][2*jp + jj];
                        MMABF16(d, ah[i][0],ah[i][1],ah[i][2],ah[i][3], bh[2*jj], bh[2*jj+1]);
                        MMABF16(d, ah[i][0],ah[i][1],ah[i][2],ah[i][3], bl[2*jj], bl[2*jj+1]);
                        MMABF16(d, al[i][0],al[i][1],al[i][2],al[i][3], bh[2*jj], bh[2*jj+1]);
                    }
                }
            }
        }
        __syncthreads();
        if (kt + 2 < nkt) { GEMM_ISSUE(kt + 2, kt & 1); CP_COMMIT; }
    }

    const int g = lane >> 2, t = lane & 3;
#pragma unroll
    for (int i = 0; i < 2; i++) {
#pragma unroll
        for (int j = 0; j < 8; j++) {
            int row = br*128 + wr*32 + i*16 + g;
            int col = bc*128 + wc*64 + j*8 + 2*t;
            *(float2*)&C[(size_t)row * N + col] = make_float2(acc[i][j][0], acc[i][j][1]);
            *(float2*)&C[(size_t)(row+8) * N + col] = make_float2(acc[i][j][2], acc[i][j][3]);
        }
    }
}

// ---------------------------------------------------------------------------
// bf16-split flash attention. BQ=128 (8 warps x 16 rows), BK=64, HD=128.
// Q pre-scaled by 1/sqrt(HD) in its planes. cp.async 2-stage on K/V.
// ---------------------------------------------------------------------------
#define F_S   136                     // plane row stride (bf16)
#define F_QH  0
#define F_QL  17408                   // 128*136
#define F_STG 34816                   // K/V stages base
#define F_KH  0
#define F_KL  8704                    // 64*136
#define F_VH  17408
#define F_VL  26112
#define F_SST 34816                   // stage stride
#define FLASH_SMEM ((F_STG + 2*F_SST)*2)   // 208896 B

__global__ __launch_bounds__(256,1) void flash_bs(
    const __nv_bfloat16* __restrict__ Qh, const __nv_bfloat16* __restrict__ Ql,
    const __nv_bfloat16* __restrict__ Kh, const __nv_bfloat16* __restrict__ Kl,
    const __nv_bfloat16* __restrict__ Vh, const __nv_bfloat16* __restrict__ Vl,
    float* __restrict__ AO)
{
    extern __shared__ __align__(16) __nv_bfloat16 smf[];
    const uint32_t smb = smem_u32(smf);

    const int tid = threadIdx.x;
    const int w = tid >> 5, lane = tid & 31;
    const int q0 = blockIdx.x * 128;
    const int b  = blockIdx.y >> 5;
    const int h  = blockIdx.y & 31;
    const int g  = h >> 2;

    // --- issue Q (once) ---
    {
        int row = tid >> 4, c = (tid & 15) * 8;   // 256 thr covers 16 rows/iter? no:
        // 2048 chunks per plane: loop
#pragma unroll
        for (int it = 0; it < 8; it++) {
            int idx = tid + it * 256;
            int r = idx >> 4, cc = (idx & 15) * 8;
            size_t go = ((size_t)((b*SEQ + q0 + r) * HQ + h)) * HD + cc;
            CP16(smb + (F_QH + r*F_S + cc)*2, Qh + go);
            CP16(smb + (F_QL + r*F_S + cc)*2, Ql + go);
        }
        (void)row; (void)c;
    }
#define FLASH_ISSUE_KV(KB, BUF) do {                                           \
    int _sb = F_STG + (BUF) * F_SST;                                           \
    _Pragma("unroll")                                                          \
    for (int _it = 0; _it < 4; _it++) {                                        \
        int _idx = tid + _it * 256;                                            \
        int _r = _idx >> 4, _c = (_idx & 15) * 8;                              \
        size_t _go = ((size_t)((b*SEQ + (KB)*64 + _r) * HK + g)) * HD + _c;    \
        CP16(smb + (_sb + F_KH + _r*F_S + _c)*2, Kh + _go);                    \
        CP16(smb + (_sb + F_KL + _r*F_S + _c)*2, Kl + _go);                    \
        CP16(smb + (_sb + F_VH + _r*F_S + _c)*2, Vh + _go);                    \
        CP16(smb + (_sb + F_VL + _r*F_S + _c)*2, Vl + _go);                    \
    } } while (0)

    FLASH_ISSUE_KV(0, 0); CP_COMMIT;
    FLASH_ISSUE_KV(1, 1); CP_COMMIT;

    float oacc[16][4];
#pragma unroll
    for (int n = 0; n < 16; n++)
#pragma unroll
        for (int r = 0; r < 4; r++) oacc[n][r] = 0.f;
    float m0 = -1e30f, m1 = -1e30f, l0 = 0.f, l1 = 0.f;

    // lane offsets
    const int q_row = w*16 + (lane & 7) + 8*((lane >> 3) & 1);
    const int q_k   = 8 * (lane >> 4);
    const int k_row = (lane & 7) + 8*(lane >> 4);          // + sp*16
    const int k_d   = 8 * ((lane >> 3) & 1);               // + dks*16
    const int v_row = (lane & 7) + 8*((lane >> 3) & 1);    // + ks*16
    const int v_d   = 8 * (lane >> 4);                     // + np*16

    const int NKB = SEQ / 64;
    for (int kb = 0; kb < NKB; kb++) {
        if (kb < NKB - 2) { CP_WAIT1; } else { CP_WAIT0; }
        __syncthreads();
        const int sb = F_STG + (kb & 1) * F_SST;

        // ---- S = Q @ K^T ----
        float sacc[8][4];
#pragma unroll
        for (int j = 0; j < 8; j++)
#pragma unroll
            for (int r = 0; r < 4; r++) sacc[j][r] = 0.f;

#pragma unroll
        for (int dks = 0; dks < 8; dks++) {
            uint32_t qh[4], ql[4];
            uint32_t qa = smb + (F_QH + q_row*F_S + dks*16 + q_k) * 2;
            LDSM4(qh[0], qh[1], qh[2], qh[3], qa);
            LDSM4(ql[0], ql[1], ql[2], ql[3], qa + (F_QL-F_QH)*2);
#pragma unroll
            for (int sp = 0; sp < 4; sp++) {
                uint32_t kh[4], kl[4];
                uint32_t ka = smb + (sb + F_KH + (sp*16 + k_row)*F_S + dks*16 + k_d) * 2;
                LDSM4(kh[0], kh[1], kh[2], kh[3], ka);
                LDSM4(kl[0], kl[1], kl[2], kl[3], ka + (F_KL-F_KH)*2);
#pragma unroll
                for (int jj = 0; jj < 2; jj++) {
                    float* d = sacc[2*sp + jj];
                    MMABF16(d, qh[0],qh[1],qh[2],qh[3], kh[2*jj], kh[2*jj+1]);
                    MMABF16(d, qh[0],qh[1],qh[2],qh[3], kl[2*jj], kl[2*jj+1]);
                    MMABF16(d, ql[0],ql[1],ql[2],ql[3], kh[2*jj], kh[2*jj+1]);
                }
            }
        }

        // ---- online softmax ----
        float mx0 = m0, mx1 = m1;
#pragma unroll
        for (int j = 0; j < 8; j++) {
            mx0 = fmaxf(mx0, fmaxf(sacc[j][0], sacc[j][1]));
            mx1 = fmaxf(mx1, fmaxf(sacc[j][2], sacc[j][3]));
        }
        mx0 = fmaxf(mx0, __shfl_xor_sync(0xffffffffu, mx0, 1));
        mx0 = fmaxf(mx0, __shfl_xor_sync(0xffffffffu, mx0, 2));
        mx1 = fmaxf(mx1, __shfl_xor_sync(0xffffffffu, mx1, 1));
        mx1 = fmaxf(mx1, __shfl_xor_sync(0xffffffffu, mx1, 2));
        float sf0 = __expf(m0 - mx0), sf1 = __expf(m1 - mx1);
        m0 = mx0; m1 = mx1;
        float rs0 = 0.f, rs1 = 0.f;
#pragma unroll
        for (int j = 0; j < 8; j++) {
            sacc[j][0] = __expf(sacc[j][0] - m0);
            sacc[j][1] = __expf(sacc[j][1] - m0);
            sacc[j][2] = __expf(sacc[j][2] - m1);
            sacc[j][3] = __expf(sacc[j][3] - m1);
            rs0 += sacc[j][0] + sacc[j][1];
            rs1 += sacc[j][2] + sacc[j][3];
        }
        rs0 += __shfl_xor_sync(0xffffffffu, rs0, 1);
        rs0 += __shfl_xor_sync(0xffffffffu, rs0, 2);
        rs1 += __shfl_xor_sync(0xffffffffu, rs1, 1);
        rs1 += __shfl_xor_sync(0xffffffffu, rs1, 2);
        l0 = l0 * sf0 + rs0;
        l1 = l1 * sf1 + rs1;
#pragma unroll
        for (int n = 0; n < 16; n++) {
            oacc[n][0] *= sf0; oacc[n][1] *= sf0;
            oacc[n][2] *= sf1; oacc[n][3] *= sf1;
        }

        // ---- O += P @ V ----
#pragma unroll
        for (int ks = 0; ks < 4; ks++) {
            uint32_t ph[4], pl[4];
            bsplit2(sacc[2*ks  ][0], sacc[2*ks  ][1], ph[0], pl[0]);
            bsplit2(sacc[2*ks  ][2], sacc[2*ks  ][3], ph[1], pl[1]);
            bsplit2(sacc[2*ks+1][0], sacc[2*ks+1][1], ph[2], pl[2]);
            bsplit2(sacc[2*ks+1][2], sacc[2*ks+1][3], ph[3], pl[3]);
#pragma unroll
            for (int np = 0; np < 8; np++) {
                uint32_t vh[4], vl[4];
                uint32_t va = smb + (sb + F_VH + (ks*16 + v_row)*F_S + np*16 + v_d) * 2;
                LDSM4T(vh[0], vh[1], vh[2], vh[3], va);
                LDSM4T(vl[0], vl[1], vl[2], vl[3], va + (F_VL-F_VH)*2);
#pragma unroll
                for (int jj = 0; jj < 2; jj++) {
                    float* d = oacc[2*np + jj];
                    MMABF16(d, ph[0],ph[1],ph[2],ph[3], vh[2*jj], vh[2*jj+1]);
                    MMABF16(d, ph[0],ph[1],ph[2],ph[3], vl[2*jj], vl[2*jj+1]);
                    MMABF16(d, pl[0],pl[1],pl[2],pl[3], vh[2*jj], vh[2*jj+1]);
                }
            }
        }
        __syncthreads();
        if (kb + 2 < NKB) { FLASH_ISSUE_KV(kb + 2, kb & 1); CP_COMMIT; }
    }

    // ---- epilogue ----
    float il0 = 1.f / l0, il1 = 1.f / l1;
    const int ga = lane >> 2, t = lane & 3;
    const int qa = q0 + w*16 + ga;
#pragma unroll
    for (int n = 0; n < 16; n++) {
        int col = n*8 + 2*t;
        size_t base0 = ((size_t)((b*SEQ + qa)     * HQ + h)) * HD + col;
        size_t base1 = ((size_t)((b*SEQ + qa + 8) * HQ + h)) * HD + col;
        *(float2*)&AO[base0] = make_float2(oacc[n][0]*il0, oacc[n][1]*il0);
        *(float2*)&AO[base1] = make_float2(oacc[n][2]*il1, oacc[n][3]*il1);
    }
}

// ---------------------------------------------------------------------------
extern "C" void kernel_launch(void* const* d_in, const int* in_sizes, int n_in,
                              void* d_out, int out_size)
{
    const float* x    = (const float*)d_in[0];
    const float* wq   = (const float*)d_in[1];
    const float* wk   = (const float*)d_in[2];
    const float* wv   = (const float*)d_in[3];
    const float* wo   = (const float*)d_in[4];
    const float* fcos = (const float*)d_in[5];
    const float* fsin = (const float*)d_in[6];
    float* out = (float*)d_out;

    float *Qp, *Kp, *Vp, *AOp;
    cudaGetSymbolAddress((void**)&Qp,  g_Q);
    cudaGetSymbolAddress((void**)&Kp,  g_K);
    cudaGetSymbolAddress((void**)&Vp,  g_V);
    cudaGetSymbolAddress((void**)&AOp, g_AO);

    __nv_bfloat16 *Xh,*Xl,*Wqh,*Wql,*Wkh,*Wkl,*Wvh,*Wvl,*Woh,*Wol;
    __nv_bfloat16 *Qh,*Ql,*Kh,*Kl,*Vh,*Vl,*AOh,*AOl;
    cudaGetSymbolAddress((void**)&Xh,  g_Xh);  cudaGetSymbolAddress((void**)&Xl,  g_Xl);
    cudaGetSymbolAddress((void**)&Wqh, g_Wqh); cudaGetSymbolAddress((void**)&Wql, g_Wql);
    cudaGetSymbolAddress((void**)&Wkh, g_Wkh); cudaGetSymbolAddress((void**)&Wkl, g_Wkl);
    cudaGetSymbolAddress((void**)&Wvh, g_Wvh); cudaGetSymbolAddress((void**)&Wvl, g_Wvl);
    cudaGetSymbolAddress((void**)&Woh, g_Woh); cudaGetSymbolAddress((void**)&Wol, g_Wol);
    cudaGetSymbolAddress((void**)&Qh,  g_Qh);  cudaGetSymbolAddress((void**)&Ql,  g_Ql);
    cudaGetSymbolAddress((void**)&Kh,  g_Kh);  cudaGetSymbolAddress((void**)&Kl,  g_Kl);
    cudaGetSymbolAddress((void**)&Vh,  g_Vh);  cudaGetSymbolAddress((void**)&Vl,  g_Vl);
    cudaGetSymbolAddress((void**)&AOh, g_AOh); cudaGetSymbolAddress((void**)&AOl, g_AOl);

    cudaFuncSetAttribute(gemm_bs, cudaFuncAttributeMaxDynamicSharedMemorySize, GEMM_SMEM);
    cudaFuncSetAttribute(flash_bs, cudaFuncAttributeMaxDynamicSharedMemorySize, FLASH_SMEM);

#define CVT(SRC, HI, LO, NELEM, SC) \
    cvt_split<<<((NELEM)/4 + 255)/256, 256>>>(SRC, HI, LO, (NELEM)/4, SC)

    // split inputs
    CVT(x,  Xh,  Xl,  (size_t)MROWS*DIM, 1.f);
    CVT(wq, Wqh, Wql, (size_t)DIM*HQ*HD, 1.f);
    CVT(wk, Wkh, Wkl, (size_t)DIM*HK*HD, 1.f);
    CVT(wv, Wvh, Wvl, (size_t)DIM*HK*HD, 1.f);
    CVT(wo, Woh, Wol, (size_t)DIM*DIM,   1.f);

    // projections
    gemm_bs<<<dim3((HQ*HD)/128, MROWS/128), 256, GEMM_SMEM>>>(Xh, Xl, Wqh, Wql, Qp, MROWS, HQ*HD, DIM);
    gemm_bs<<<dim3((HK*HD)/128, MROWS/128), 256, GEMM_SMEM>>>(Xh, Xl, Wkh, Wkl, Kp, MROWS, HK*HD, DIM);
    gemm_bs<<<dim3((HK*HD)/128, MROWS/128), 256, GEMM_SMEM>>>(Xh, Xl, Wvh, Wvl, Vp, MROWS, HK*HD, DIM);

    // RoPE
    {
        int nq = BATCH * SEQ * HQ * (HD / 2);
        rope_kernel<<<(nq + 255) / 256, 256>>>(Qp, fcos, fsin, HQ, nq);
        int nk = BATCH * SEQ * HK * (HD / 2);
        rope_kernel<<<(nk + 255) / 256, 256>>>(Kp, fcos, fsin, HK, nk);
    }

    // split Q (with softmax scale), K, V
    CVT(Qp, Qh, Ql, (size_t)MROWS*HQ*HD, 0.08838834764831845f);
    CVT(Kp, Kh, Kl, (size_t)MROWS*HK*HD, 1.f);
    CVT(Vp, Vh, Vl, (size_t)MROWS*HK*HD, 1.f);

    // flash attention
    flash_bs<<<dim3(SEQ/128, BATCH*HQ), 256, FLASH_SMEM>>>(Qh, Ql, Kh, Kl, Vh, Vl, AOp);

    // split AO, output projection
    CVT(AOp, AOh, AOl, (size_t)MROWS*HQ*HD, 1.f);
    gemm_bs<<<dim3(DIM/128, MROWS/128), 256, GEMM_SMEM>>>(AOh, AOl, Woh, Wol, out, MROWS, DIM, DIM);
}

// round 5
// speedup vs baseline: 4.2354x; 1.0466x over previous
#include <cuda_runtime.h>
#include <cuda_bf16.h>
#include <math.h>
#include <stdint.h>

#define BATCH 2
#define SEQ   2048
#define DIM   4096
#define HQ    32
#define HK    8
#define HD    128
#define REP   4
#define MROWS (BATCH*SEQ)   // 4096

// bf16 hi/lo planes (row-major [M,K] per plane)
__device__ __nv_bfloat16 g_Xh [(size_t)MROWS*DIM],   g_Xl [(size_t)MROWS*DIM];
__device__ __nv_bfloat16 g_Wqh[(size_t)DIM*HQ*HD],   g_Wql[(size_t)DIM*HQ*HD];
__device__ __nv_bfloat16 g_Wkh[(size_t)DIM*HK*HD],   g_Wkl[(size_t)DIM*HK*HD];
__device__ __nv_bfloat16 g_Wvh[(size_t)DIM*HK*HD],   g_Wvl[(size_t)DIM*HK*HD];
__device__ __nv_bfloat16 g_Woh[(size_t)DIM*DIM],     g_Wol[(size_t)DIM*DIM];
__device__ __nv_bfloat16 g_Qh [(size_t)MROWS*HQ*HD], g_Ql [(size_t)MROWS*HQ*HD];
__device__ __nv_bfloat16 g_Kh [(size_t)MROWS*HK*HD], g_Kl [(size_t)MROWS*HK*HD];
__device__ __nv_bfloat16 g_Vh [(size_t)MROWS*HK*HD], g_Vl [(size_t)MROWS*HK*HD];
__device__ __nv_bfloat16 g_AOh[(size_t)MROWS*HQ*HD], g_AOl[(size_t)MROWS*HQ*HD];

// ---------------- PTX helpers ----------------
#define LDSM4(R0,R1,R2,R3,A) \
    asm volatile("ldmatrix.sync.aligned.m8n8.x4.shared.b16 {%0,%1,%2,%3},[%4];" \
        : "=r"(R0),"=r"(R1),"=r"(R2),"=r"(R3) : "r"(A))
#define LDSM4T(R0,R1,R2,R3,A) \
    asm volatile("ldmatrix.sync.aligned.m8n8.x4.trans.shared.b16 {%0,%1,%2,%3},[%4];" \
        : "=r"(R0),"=r"(R1),"=r"(R2),"=r"(R3) : "r"(A))
#define MMABF16(D,A0,A1,A2,A3,B0,B1) \
    asm volatile("mma.sync.aligned.m16n8k16.row.col.f32.bf16.bf16.f32 " \
        "{%0,%1,%2,%3},{%4,%5,%6,%7},{%8,%9},{%0,%1,%2,%3};" \
        : "+f"(D[0]),"+f"(D[1]),"+f"(D[2]),"+f"(D[3]) \
        : "r"(A0),"r"(A1),"r"(A2),"r"(A3),"r"(B0),"r"(B1))
#define CP16(DST,SRC) \
    asm volatile("cp.async.cg.shared.global [%0],[%1],16;" :: "r"(DST),"l"(SRC))
#define CP_COMMIT asm volatile("cp.async.commit_group;" ::: "memory")
#define CP_WAIT1  asm volatile("cp.async.wait_group 1;" ::: "memory")
#define CP_WAIT0  asm volatile("cp.async.wait_group 0;" ::: "memory")

__device__ __forceinline__ uint32_t smem_u32(const void* p) {
    return (uint32_t)__cvta_generic_to_shared(p);
}
__device__ __forceinline__ void bsplit2(float x0, float x1, uint32_t& h, uint32_t& l) {
    __nv_bfloat16 h0 = __float2bfloat16(x0), h1 = __float2bfloat16(x1);
    float r0 = x0 - __bfloat162float(h0), r1 = x1 - __bfloat162float(h1);
    __nv_bfloat162 hh; hh.x = h0; hh.y = h1;
    __nv_bfloat162 ll; ll.x = __float2bfloat16(r0); ll.y = __float2bfloat16(r1);
    h = *(uint32_t*)&hh; l = *(uint32_t*)&ll;
}

// ---------------------------------------------------------------------------
// Split fp32 -> (hi, lo) bf16 planes (inputs only).
// ---------------------------------------------------------------------------
__global__ void cvt_split(const float* __restrict__ src,
                          __nv_bfloat16* __restrict__ hi,
                          __nv_bfloat16* __restrict__ lo, int n4)
{
    int i = blockIdx.x * blockDim.x + threadIdx.x;
    if (i >= n4) return;
    float4 v = ((const float4*)src)[i];
    uint32_t h01, l01, h23, l23;
    bsplit2(v.x, v.y, h01, l01);
    bsplit2(v.z, v.w, h23, l23);
    ((uint2*)hi)[i] = make_uint2(h01, h23);
    ((uint2*)lo)[i] = make_uint2(l01, l23);
}

// ---------------------------------------------------------------------------
// bf16-split GEMM with fused epilogues.
// MODE 0: write fp32 C.   MODE 1: split -> (Oh, Ol).   MODE 2: rope*scale ->
// split -> (Oh, Ol).  128x128x32 tile, 256 thr, cp.async 2-stage, ldmatrix.
// ---------------------------------------------------------------------------
#define G_SA 40
#define G_SB 136
#define G_AH 0
#define G_AL 5120
#define G_BH 10240
#define G_BL 14592
#define G_ST 18944
#define GEMM_SMEM (2*G_ST*2)

template<int MODE>
__global__ __launch_bounds__(256,2) void gemm_bs(
    const __nv_bfloat16* __restrict__ Ah, const __nv_bfloat16* __restrict__ Al,
    const __nv_bfloat16* __restrict__ Bh, const __nv_bfloat16* __restrict__ Bl,
    float* __restrict__ C,
    __nv_bfloat16* __restrict__ Oh, __nv_bfloat16* __restrict__ Ol,
    const float* __restrict__ cosv, const float* __restrict__ sinv, float scale,
    int M, int N, int K)
{
    extern __shared__ __align__(16) __nv_bfloat16 smg[];
    const uint32_t smb = smem_u32(smg);

    const int tid  = threadIdx.x;
    const int br = blockIdx.y, bc = blockIdx.x;
    const int warp = tid >> 5, lane = tid & 31;
    const int wr = warp & 3, wc = warp >> 2;

    float acc[2][8][4];
#pragma unroll
    for (int i = 0; i < 2; i++)
#pragma unroll
        for (int j = 0; j < 8; j++)
#pragma unroll
            for (int r = 0; r < 4; r++) acc[i][j][r] = 0.f;

    const int a_row = (lane & 7) + 8 * ((lane >> 3) & 1);
    const int a_k   = 8 * (lane >> 4);
    const int b_kr  = (lane & 7) + 8 * ((lane >> 3) & 1);
    const int b_n   = 8 * (lane >> 4);

    const int nkt = K / 32;

    const int ar0 = tid >> 2, ac0 = (tid & 3) * 8;
    const int bk0 = tid >> 4, bn0 = (tid & 15) * 8;
#define GEMM_ISSUE(KT, BUF) do {                                               \
    int _sb = (BUF) * G_ST;                                                    \
    _Pragma("unroll")                                                          \
    for (int _j = 0; _j < 2; _j++) {                                           \
        int _r = ar0 + _j * 64;                                                \
        size_t _go = (size_t)(br*128 + _r) * K + (KT)*32 + ac0;                \
        CP16(smb + (_sb + G_AH + _r*G_SA + ac0)*2, Ah + _go);                  \
        CP16(smb + (_sb + G_AL + _r*G_SA + ac0)*2, Al + _go);                  \
        int _k = bk0 + _j * 16;                                                \
        size_t _gb = (size_t)((KT)*32 + _k) * N + bc*128 + bn0;                \
        CP16(smb + (_sb + G_BH + _k*G_SB + bn0)*2, Bh + _gb);                  \
        CP16(smb + (_sb + G_BL + _k*G_SB + bn0)*2, Bl + _gb);                  \
    } } while (0)

    GEMM_ISSUE(0, 0); CP_COMMIT;
    if (nkt > 1) { GEMM_ISSUE(1, 1); } CP_COMMIT;

    for (int kt = 0; kt < nkt; kt++) {
        if (kt < nkt - 2) { CP_WAIT1; } else { CP_WAIT0; }
        __syncthreads();
        const int sb = (kt & 1) * G_ST;

#pragma unroll
        for (int ks = 0; ks < 2; ks++) {
            uint32_t ah[2][4], al[2][4];
#pragma unroll
            for (int i = 0; i < 2; i++) {
                uint32_t addr = smb + (sb + G_AH +
                    (wr*32 + i*16 + a_row)*G_SA + ks*16 + a_k) * 2;
                LDSM4(ah[i][0], ah[i][1], ah[i][2], ah[i][3], addr);
                LDSM4(al[i][0], al[i][1], al[i][2], al[i][3], addr + (G_AL-G_AH)*2);
            }
#pragma unroll
            for (int jp = 0; jp < 4; jp++) {
                uint32_t bh[4], bl[4];
                uint32_t addr = smb + (sb + G_BH +
                    (ks*16 + b_kr)*G_SB + wc*64 + jp*16 + b_n) * 2;
                LDSM4T(bh[0], bh[1], bh[2], bh[3], addr);
                LDSM4T(bl[0], bl[1], bl[2], bl[3], addr + (G_BL-G_BH)*2);
#pragma unroll
                for (int i = 0; i < 2; i++) {
#pragma unroll
                    for (int jj = 0; jj < 2; jj++) {
                        float* d = acc[i][2*jp + jj];
                        MMABF16(d, ah[i][0],ah[i][1],ah[i][2],ah[i][3], bh[2*jj], bh[2*jj+1]);
                        MMABF16(d, ah[i][0],ah[i][1],ah[i][2],ah[i][3], bl[2*jj], bl[2*jj+1]);
                        MMABF16(d, al[i][0],al[i][1],al[i][2],al[i][3], bh[2*jj], bh[2*jj+1]);
                    }
                }
            }
        }
        __syncthreads();
        if (kt + 2 < nkt) { GEMM_ISSUE(kt + 2, kt & 1); CP_COMMIT; }
    }

    const int g = lane >> 2, t = lane & 3;
#pragma unroll
    for (int i = 0; i < 2; i++) {
#pragma unroll
        for (int j = 0; j < 8; j++) {
            int row = br*128 + wr*32 + i*16 + g;
            int col = bc*128 + wc*64 + j*8 + 2*t;
            float a0 = acc[i][j][0], a1 = acc[i][j][1];
            float a2 = acc[i][j][2], a3 = acc[i][j][3];
            if (MODE == 0) {
                *(float2*)&C[(size_t)row * N + col] = make_float2(a0, a1);
                *(float2*)&C[(size_t)(row+8) * N + col] = make_float2(a2, a3);
            } else {
                if (MODE == 2) {
                    int s0 = row & (SEQ-1), s1 = (row+8) & (SEQ-1);
                    int d2 = (col & (HD-1)) >> 1;
                    float c0 = cosv[s0*64 + d2], sn0 = sinv[s0*64 + d2];
                    float c1 = cosv[s1*64 + d2], sn1 = sinv[s1*64 + d2];
                    float r;
                    r  = (a0*c0 - a1*sn0) * scale;
                    a1 = (a0*sn0 + a1*c0) * scale;  a0 = r;
                    r  = (a2*c1 - a3*sn1) * scale;
                    a3 = (a2*sn1 + a3*c1) * scale;  a2 = r;
                }
                uint32_t h0, l0, h1, l1;
                bsplit2(a0, a1, h0, l0);
                bsplit2(a2, a3, h1, l1);
                *(uint32_t*)&Oh[(size_t)row * N + col] = h0;
                *(uint32_t*)&Ol[(size_t)row * N + col] = l0;
                *(uint32_t*)&Oh[(size_t)(row+8) * N + col] = h1;
                *(uint32_t*)&Ol[(size_t)(row+8) * N + col] = l1;
            }
        }
    }
}

// ---------------------------------------------------------------------------
// bf16-split flash attention. BQ=128, BK=64, HD=128. Q fragments hoisted to
// registers; AO written as hi/lo bf16 planes directly.
// ---------------------------------------------------------------------------
#define F_S   136
#define F_QH  0
#define F_QL  17408
#define F_STG 34816
#define F_KH  0
#define F_KL  8704
#define F_VH  17408
#define F_VL  26112
#define F_SST 34816
#define FLASH_SMEM ((F_STG + 2*F_SST)*2)

__global__ __launch_bounds__(256,1) void flash_bs(
    const __nv_bfloat16* __restrict__ Qh, const __nv_bfloat16* __restrict__ Ql,
    const __nv_bfloat16* __restrict__ Kh, const __nv_bfloat16* __restrict__ Kl,
    const __nv_bfloat16* __restrict__ Vh, const __nv_bfloat16* __restrict__ Vl,
    __nv_bfloat16* __restrict__ AOh, __nv_bfloat16* __restrict__ AOl)
{
    extern __shared__ __align__(16) __nv_bfloat16 smf[];
    const uint32_t smb = smem_u32(smf);

    const int tid = threadIdx.x;
    const int w = tid >> 5, lane = tid & 31;
    const int q0 = blockIdx.x * 128;
    const int b  = blockIdx.y >> 5;
    const int h  = blockIdx.y & 31;
    const int g  = h >> 2;

#pragma unroll
    for (int it = 0; it < 8; it++) {
        int idx = tid + it * 256;
        int r = idx >> 4, cc = (idx & 15) * 8;
        size_t go = ((size_t)((b*SEQ + q0 + r) * HQ + h)) * HD + cc;
        CP16(smb + (F_QH + r*F_S + cc)*2, Qh + go);
        CP16(smb + (F_QL + r*F_S + cc)*2, Ql + go);
    }
#define FLASH_ISSUE_KV(KB, BUF) do {                                           \
    int _sb = F_STG + (BUF) * F_SST;                                           \
    _Pragma("unroll")                                                          \
    for (int _it = 0; _it < 4; _it++) {                                        \
        int _idx = tid + _it * 256;                                            \
        int _r = _idx >> 4, _c = (_idx & 15) * 8;                              \
        size_t _go = ((size_t)((b*SEQ + (KB)*64 + _r) * HK + g)) * HD + _c;    \
        CP16(smb + (_sb + F_KH + _r*F_S + _c)*2, Kh + _go);                    \
        CP16(smb + (_sb + F_KL + _r*F_S + _c)*2, Kl + _go);                    \
        CP16(smb + (_sb + F_VH + _r*F_S + _c)*2, Vh + _go);                    \
        CP16(smb + (_sb + F_VL + _r*F_S + _c)*2, Vl + _go);                    \
    } } while (0)

    FLASH_ISSUE_KV(0, 0); CP_COMMIT;
    FLASH_ISSUE_KV(1, 1); CP_COMMIT;

    float oacc[16][4];
#pragma unroll
    for (int n = 0; n < 16; n++)
#pragma unroll
        for (int r = 0; r < 4; r++) oacc[n][r] = 0.f;
    float m0 = -1e30f, m1 = -1e30f, l0 = 0.f, l1 = 0.f;

    const int q_row = w*16 + (lane & 7) + 8*((lane >> 3) & 1);
    const int q_k   = 8 * (lane >> 4);
    const int k_row = (lane & 7) + 8*(lane >> 4);
    const int k_d   = 8 * ((lane >> 3) & 1);
    const int v_row = (lane & 7) + 8*((lane >> 3) & 1);
    const int v_d   = 8 * (lane >> 4);

    uint32_t qfh[8][4], qfl[8][4];   // hoisted Q fragments

    const int NKB = SEQ / 64;
    for (int kb = 0; kb < NKB; kb++) {
        if (kb < NKB - 2) { CP_WAIT1; } else { CP_WAIT0; }
        __syncthreads();
        const int sb = F_STG + (kb & 1) * F_SST;

        if (kb == 0) {
#pragma unroll
            for (int dks = 0; dks < 8; dks++) {
                uint32_t qa = smb + (F_QH + q_row*F_S + dks*16 + q_k) * 2;
                LDSM4(qfh[dks][0], qfh[dks][1], qfh[dks][2], qfh[dks][3], qa);
                LDSM4(qfl[dks][0], qfl[dks][1], qfl[dks][2], qfl[dks][3],
                      qa + (F_QL-F_QH)*2);
            }
        }

        float sacc[8][4];
#pragma unroll
        for (int j = 0; j < 8; j++)
#pragma unroll
            for (int r = 0; r < 4; r++) sacc[j][r] = 0.f;

#pragma unroll
        for (int dks = 0; dks < 8; dks++) {
#pragma unroll
            for (int sp = 0; sp < 4; sp++) {
                uint32_t kh[4], kl[4];
                uint32_t ka = smb + (sb + F_KH + (sp*16 + k_row)*F_S + dks*16 + k_d) * 2;
                LDSM4(kh[0], kh[1], kh[2], kh[3], ka);
                LDSM4(kl[0], kl[1], kl[2], kl[3], ka + (F_KL-F_KH)*2);
#pragma unroll
                for (int jj = 0; jj < 2; jj++) {
                    float* d = sacc[2*sp + jj];
                    MMABF16(d, qfh[dks][0],qfh[dks][1],qfh[dks][2],qfh[dks][3], kh[2*jj], kh[2*jj+1]);
                    MMABF16(d, qfh[dks][0],qfh[dks][1],qfh[dks][2],qfh[dks][3], kl[2*jj], kl[2*jj+1]);
                    MMABF16(d, qfl[dks][0],qfl[dks][1],qfl[dks][2],qfl[dks][3], kh[2*jj], kh[2*jj+1]);
                }
            }
        }

        float mx0 = m0, mx1 = m1;
#pragma unroll
        for (int j = 0; j < 8; j++) {
            mx0 = fmaxf(mx0, fmaxf(sacc[j][0], sacc[j][1]));
            mx1 = fmaxf(mx1, fmaxf(sacc[j][2], sacc[j][3]));
        }
        mx0 = fmaxf(mx0, __shfl_xor_sync(0xffffffffu, mx0, 1));
        mx0 = fmaxf(mx0, __shfl_xor_sync(0xffffffffu, mx0, 2));
        mx1 = fmaxf(mx1, __shfl_xor_sync(0xffffffffu, mx1, 1));
        mx1 = fmaxf(mx1, __shfl_xor_sync(0xffffffffu, mx1, 2));
        float sf0 = __expf(m0 - mx0), sf1 = __expf(m1 - mx1);
        m0 = mx0; m1 = mx1;
        float rs0 = 0.f, rs1 = 0.f;
#pragma unroll
        for (int j = 0; j < 8; j++) {
            sacc[j][0] = __expf(sacc[j][0] - m0);
            sacc[j][1] = __expf(sacc[j][1] - m0);
            sacc[j][2] = __expf(sacc[j][2] - m1);
            sacc[j][3] = __expf(sacc[j][3] - m1);
            rs0 += sacc[j][0] + sacc[j][1];
            rs1 += sacc[j][2] + sacc[j][3];
        }
        rs0 += __shfl_xor_sync(0xffffffffu, rs0, 1);
        rs0 += __shfl_xor_sync(0xffffffffu, rs0, 2);
        rs1 += __shfl_xor_sync(0xffffffffu, rs1, 1);
        rs1 += __shfl_xor_sync(0xffffffffu, rs1, 2);
        l0 = l0 * sf0 + rs0;
        l1 = l1 * sf1 + rs1;
#pragma unroll
        for (int n = 0; n < 16; n++) {
            oacc[n][0] *= sf0; oacc[n][1] *= sf0;
            oacc[n][2] *= sf1; oacc[n][3] *= sf1;
        }

#pragma unroll
        for (int ks = 0; ks < 4; ks++) {
            uint32_t ph[4], pl[4];
            bsplit2(sacc[2*ks  ][0], sacc[2*ks  ][1], ph[0], pl[0]);
            bsplit2(sacc[2*ks  ][2], sacc[2*ks  ][3], ph[1], pl[1]);
            bsplit2(sacc[2*ks+1][0], sacc[2*ks+1][1], ph[2], pl[2]);
            bsplit2(sacc[2*ks+1][2], sacc[2*ks+1][3], ph[3], pl[3]);
#pragma unroll
            for (int np = 0; np < 8; np++) {
                uint32_t vh[4], vl[4];
                uint32_t va = smb + (sb + F_VH + (ks*16 + v_row)*F_S + np*16 + v_d) * 2;
                LDSM4T(vh[0], vh[1], vh[2], vh[3], va);
                LDSM4T(vl[0], vl[1], vl[2], vl[3], va + (F_VL-F_VH)*2);
#pragma unroll
                for (int jj = 0; jj < 2; jj++) {
                    float* d = oacc[2*np + jj];
                    MMABF16(d, ph[0],ph[1],ph[2],ph[3], vh[2*jj], vh[2*jj+1]);
                    MMABF16(d, ph[0],ph[1],ph[2],ph[3], vl[2*jj], vl[2*jj+1]);
                    MMABF16(d, pl[0],pl[1],pl[2],pl[3], vh[2*jj], vh[2*jj+1]);
                }
            }
        }
        __syncthreads();
        if (kb + 2 < NKB) { FLASH_ISSUE_KV(kb + 2, kb & 1); CP_COMMIT; }
    }

    // epilogue: split to hi/lo planes directly
    float il0 = 1.f / l0, il1 = 1.f / l1;
    const int ga = lane >> 2, t = lane & 3;
    const int qa = q0 + w*16 + ga;
#pragma unroll
    for (int n = 0; n < 16; n++) {
        int col = n*8 + 2*t;
        size_t base0 = ((size_t)((b*SEQ + qa)     * HQ + h)) * HD + col;
        size_t base1 = ((size_t)((b*SEQ + qa + 8) * HQ + h)) * HD + col;
        uint32_t hh, ll;
        bsplit2(oacc[n][0]*il0, oacc[n][1]*il0, hh, ll);
        *(uint32_t*)&AOh[base0] = hh;
        *(uint32_t*)&AOl[base0] = ll;
        bsplit2(oacc[n][2]*il1, oacc[n][3]*il1, hh, ll);
        *(uint32_t*)&AOh[base1] = hh;
        *(uint32_t*)&AOl[base1] = ll;
    }
}

// ---------------------------------------------------------------------------
extern "C" void kernel_launch(void* const* d_in, const int* in_sizes, int n_in,
                              void* d_out, int out_size)
{
    const float* x    = (const float*)d_in[0];
    const float* wq   = (const float*)d_in[1];
    const float* wk   = (const float*)d_in[2];
    const float* wv   = (const float*)d_in[3];
    const float* wo   = (const float*)d_in[4];
    const float* fcos = (const float*)d_in[5];
    const float* fsin = (const float*)d_in[6];
    float* out = (float*)d_out;

    __nv_bfloat16 *Xh,*Xl,*Wqh,*Wql,*Wkh,*Wkl,*Wvh,*Wvl,*Woh,*Wol;
    __nv_bfloat16 *Qh,*Ql,*Kh,*Kl,*Vh,*Vl,*AOh,*AOl;
    cudaGetSymbolAddress((void**)&Xh,  g_Xh);  cudaGetSymbolAddress((void**)&Xl,  g_Xl);
    cudaGetSymbolAddress((void**)&Wqh, g_Wqh); cudaGetSymbolAddress((void**)&Wql, g_Wql);
    cudaGetSymbolAddress((void**)&Wkh, g_Wkh); cudaGetSymbolAddress((void**)&Wkl, g_Wkl);
    cudaGetSymbolAddress((void**)&Wvh, g_Wvh); cudaGetSymbolAddress((void**)&Wvl, g_Wvl);
    cudaGetSymbolAddress((void**)&Woh, g_Woh); cudaGetSymbolAddress((void**)&Wol, g_Wol);
    cudaGetSymbolAddress((void**)&Qh,  g_Qh);  cudaGetSymbolAddress((void**)&Ql,  g_Ql);
    cudaGetSymbolAddress((void**)&Kh,  g_Kh);  cudaGetSymbolAddress((void**)&Kl,  g_Kl);
    cudaGetSymbolAddress((void**)&Vh,  g_Vh);  cudaGetSymbolAddress((void**)&Vl,  g_Vl);
    cudaGetSymbolAddress((void**)&AOh, g_AOh); cudaGetSymbolAddress((void**)&AOl, g_AOl);

    cudaFuncSetAttribute(gemm_bs<0>, cudaFuncAttributeMaxDynamicSharedMemorySize, GEMM_SMEM);
    cudaFuncSetAttribute(gemm_bs<1>, cudaFuncAttributeMaxDynamicSharedMemorySize, GEMM_SMEM);
    cudaFuncSetAttribute(gemm_bs<2>, cudaFuncAttributeMaxDynamicSharedMemorySize, GEMM_SMEM);
    cudaFuncSetAttribute(flash_bs,   cudaFuncAttributeMaxDynamicSharedMemorySize, FLASH_SMEM);

    // split raw inputs into hi/lo planes
#define CVT(SRC, HI, LO, NELEM) \
    cvt_split<<<(int)(((NELEM)/4 + 255)/256), 256>>>(SRC, HI, LO, (int)((NELEM)/4))
    CVT(x,  Xh,  Xl,  (size_t)MROWS*DIM);
    CVT(wq, Wqh, Wql, (size_t)DIM*HQ*HD);
    CVT(wk, Wkh, Wkl, (size_t)DIM*HK*HD);
    CVT(wv, Wvh, Wvl, (size_t)DIM*HK*HD);
    CVT(wo, Woh, Wol, (size_t)DIM*DIM);

    // projections with fused rope+split epilogues
    gemm_bs<2><<<dim3((HQ*HD)/128, MROWS/128), 256, GEMM_SMEM>>>(
        Xh, Xl, Wqh, Wql, nullptr, Qh, Ql, fcos, fsin,
        0.08838834764831845f, MROWS, HQ*HD, DIM);
    gemm_bs<2><<<dim3((HK*HD)/128, MROWS/128), 256, GEMM_SMEM>>>(
        Xh, Xl, Wkh, Wkl, nullptr, Kh, Kl, fcos, fsin, 1.f, MROWS, HK*HD, DIM);
    gemm_bs<1><<<dim3((HK*HD)/128, MROWS/128), 256, GEMM_SMEM>>>(
        Xh, Xl, Wvh, Wvl, nullptr, Vh, Vl, nullptr, nullptr, 1.f, MROWS, HK*HD, DIM);

    // flash attention -> AO hi/lo planes
    flash_bs<<<dim3(SEQ/128, BATCH*HQ), 256, FLASH_SMEM>>>(
        Qh, Ql, Kh, Kl, Vh, Vl, AOh, AOl);

    // output projection (fp32 out)
    gemm_bs<0><<<dim3(DIM/128, MROWS/128), 256, GEMM_SMEM>>>(
        AOh, AOl, Woh, Wol, out, nullptr, nullptr, nullptr, nullptr, 1.f,
        MROWS, DIM, DIM);
}